// round 13
// baseline (speedup 1.0000x reference)
#include <cuda_runtime.h>
#include <cstdint>
#include <math.h>
#include <cuda_fp16.h>
#include <mma.h>
using namespace nvcuda;

// Fixed problem shapes
#define BB   4
#define SS   4096
#define DDIM 512
#define HH   2048
#define LL   3
#define MMR  (BB*SS)      // 16384 rows
#define CHK  128          // scan chunk length (per-thread serial)
#define NCH  (SS/CHK)     // 32 chunks per sequence

// GEMM tiling: 128x128 CTA tile, 4 warps (64x64 each), KTILE=64, 2 CTAs/SM
#define KTILE 64
#define LDSA  72          // smem stride in halfs (64 + 8 pad)
#define ATILE (128*LDSA)  // 9216 halfs = 18432 B
#define EPIOFF (4*ATILE)  // halfs offset where epilogue staging begins
#define SMEMSZ (4*ATILE*2 + 4*256*4)   // 73728 + 4096 = 77824 bytes
#define NTHR  128

// ---------------- scratch (static device arrays; no allocation) --------------
__device__ float  g_xbuf[MMR*DDIM];   // residual stream (fp32)
__device__ float  g_P [BB*DDIM*NCH];
__device__ float  g_V [BB*DDIM*NCH];
__device__ float  g_Hi[BB*DDIM*NCH];
__device__ __half g_c16 [MMR*DDIM];   // gate c (fp16)
__device__ __half g_v16 [MMR*DDIM];   // gate v (fp16)
__device__ __half g_gin16[MMR*DDIM];  // LN outputs (GEMM A operand)
__device__ __half g_cin16[MMR*DDIM];  // dwconv out / mlp_in (GEMM A operand)
__device__ __half g_h16 [MMR*HH];     // MLP hidden (fp16)
// fp16 transposed weights [N][K]
__device__ __half g_Wzh16[LL*2*DDIM*DDIM];  // interleaved [1024][512] per layer
__device__ __half g_W1T16[HH*DDIM];
__device__ __half g_W2T16[DDIM*HH];
__device__ __half g_pw16 [DDIM*DDIM];

// ---------------- fp16 tensor-core GEMM, 128x128x64, 4 warps of 64x64 --------
// C[m,n] = sum_k A[m,k] * Bt[n,k]   (A fp16 [M,K], Bt fp16 [N,K], fp32 accum)
__device__ __forceinline__ void cpasync16(void* dst, const void* src)
{
    unsigned int d = (unsigned int)__cvta_generic_to_shared(dst);
    asm volatile("cp.async.cg.shared.global [%0], [%1], 16;\n" :: "r"(d), "l"(src));
}

__global__ void __launch_bounds__(NTHR, 2)
hgemm_kernel(const __half* __restrict__ A, const __half* __restrict__ Bt,
             float* __restrict__ C, __half* __restrict__ C16,
             __half* __restrict__ gateC, __half* __restrict__ gateV,
             int M, int N, int K,
             const float* __restrict__ bias, const float* __restrict__ resid,
             int dorelu)
{
    extern __shared__ __half smh[];
    __half* Asm[2] = { smh, smh + ATILE };
    __half* Bsm[2] = { smh + 2*ATILE, smh + 3*ATILE };
    float*  epist  = (float*)(smh + EPIOFF);

    const int tid = threadIdx.x;
    const int wid = tid >> 5;
    const int lane = tid & 31;
    const int bm = blockIdx.y * 128;
    const int bn = blockIdx.x * 128;
    const int wm = (wid >> 1) * 64;   // warp grid 2(m) x 2(n)
    const int wn = (wid & 1) * 64;
    float* wbuf = epist + wid*256;    // per-warp 16x16 staging

    wmma::fragment<wmma::accumulator, 16, 16, 16, float> acc[4][4];
    #pragma unroll
    for (int i = 0; i < 4; i++)
        #pragma unroll
        for (int j = 0; j < 4; j++) wmma::fill_fragment(acc[i][j], 0.f);

    // ---- tile loaders: 128 rows x 64 halfs = 1024 16B-chunks -> 8/thread ----
    auto loadA = [&](int buf, int k0) {
        #pragma unroll
        for (int i = 0; i < 8; i++) {
            int idx = tid + i*NTHR;
            int r = idx >> 3, c8 = (idx & 7) * 8;   // halfs
            cpasync16(Asm[buf] + r*LDSA + c8, A + (size_t)(bm + r)*K + k0 + c8);
        }
    };
    auto loadB = [&](int buf, int k0) {
        #pragma unroll
        for (int i = 0; i < 8; i++) {
            int idx = tid + i*NTHR;
            int r = idx >> 3, c8 = (idx & 7) * 8;
            cpasync16(Bsm[buf] + r*LDSA + c8, Bt + (size_t)(bn + r)*K + k0 + c8);
        }
    };

    const int nk = K / KTILE;
    loadA(0, 0); loadB(0, 0);
    asm volatile("cp.async.commit_group;\n");

    for (int kt = 0; kt < nk; kt++) {
        if (kt + 1 < nk) {
            loadA((kt+1)&1, (kt+1)*KTILE);
            loadB((kt+1)&1, (kt+1)*KTILE);
            asm volatile("cp.async.commit_group;\n");
            asm volatile("cp.async.wait_group 1;\n");
        } else {
            asm volatile("cp.async.wait_group 0;\n");
        }
        __syncthreads();

        const __half* a = Asm[kt&1];
        const __half* b = Bsm[kt&1];
        #pragma unroll
        for (int ks = 0; ks < 4; ks++) {
            const int kk = ks * 16;
            wmma::fragment<wmma::matrix_a, 16, 16, 16, half, wmma::row_major> af[4];
            #pragma unroll
            for (int i = 0; i < 4; i++)
                wmma::load_matrix_sync(af[i], a + (wm + i*16)*LDSA + kk, LDSA);
            wmma::fragment<wmma::matrix_b, 16, 16, 16, half, wmma::col_major> bf[4];
            #pragma unroll
            for (int j = 0; j < 4; j++)
                wmma::load_matrix_sync(bf[j], b + (wn + j*16)*LDSA + kk, LDSA);
            #pragma unroll
            for (int i = 0; i < 4; i++)
                #pragma unroll
                for (int j = 0; j < 4; j++)
                    wmma::mma_sync(acc[i][j], af[i], bf[j], acc[i][j]);
        }
        __syncthreads();
    }

    // ---- epilogue: per-warp 16x16 staging ----
    #pragma unroll
    for (int i = 0; i < 4; i++) {
        #pragma unroll
        for (int j = 0; j < 4; j++) {
            wmma::store_matrix_sync(wbuf, acc[i][j], 16, wmma::mem_row_major);
            __syncwarp();
            int r = lane >> 1, c = (lane & 1) * 8;
            int row = bm + wm + i*16 + r;
            int col = bn + wn + j*16 + c;
            float4 v0 = *(float4*)&wbuf[r*16 + c];
            float4 v1 = *(float4*)&wbuf[r*16 + c + 4];
            if (gateC) {
                // interleaved cols: (k0,a0,k1,a1,...) -> 4 (k,a) pairs
                float kk_[4] = { v0.x, v0.z, v1.x, v1.z };
                float aa_[4] = { v0.y, v0.w, v1.y, v1.w };
                __half cw[4], vw[4];
                #pragma unroll
                for (int t = 0; t < 4; t++) {
                    float e  = __expf(kk_[t]);
                    float ci = 1.f / (1.f + e);      // sigmoid(-k)
                    float zi = e * ci;               // sigmoid(k)
                    float a  = aa_[t];
                    float gg = (a >= 0.f) ? (a + 0.5f)
                                          : (1.f / (1.f + __expf(-a)));
                    cw[t] = __float2half(ci);
                    vw[t] = __float2half(zi * gg);
                }
                int p = col >> 1;    // pair index 0..511
                *(uint2*)&gateC[(size_t)row*DDIM + p] = *(uint2*)cw;
                *(uint2*)&gateV[(size_t)row*DDIM + p] = *(uint2*)vw;
            } else {
                if (bias) {
                    float4 b0 = *(const float4*)&bias[col];
                    float4 b1 = *(const float4*)&bias[col+4];
                    v0.x += b0.x; v0.y += b0.y; v0.z += b0.z; v0.w += b0.w;
                    v1.x += b1.x; v1.y += b1.y; v1.z += b1.z; v1.w += b1.w;
                }
                if (dorelu) {
                    v0.x = fmaxf(v0.x, 0.f); v0.y = fmaxf(v0.y, 0.f);
                    v0.z = fmaxf(v0.z, 0.f); v0.w = fmaxf(v0.w, 0.f);
                    v1.x = fmaxf(v1.x, 0.f); v1.y = fmaxf(v1.y, 0.f);
                    v1.z = fmaxf(v1.z, 0.f); v1.w = fmaxf(v1.w, 0.f);
                }
                if (resid) {
                    float4 r0 = *(const float4*)&resid[(size_t)row*N + col];
                    float4 r1 = *(const float4*)&resid[(size_t)row*N + col + 4];
                    v0.x += r0.x; v0.y += r0.y; v0.z += r0.z; v0.w += r0.w;
                    v1.x += r1.x; v1.y += r1.y; v1.z += r1.z; v1.w += r1.w;
                }
                if (C16) {
                    __half2 h[4];
                    h[0] = __floats2half2_rn(v0.x, v0.y);
                    h[1] = __floats2half2_rn(v0.z, v0.w);
                    h[2] = __floats2half2_rn(v1.x, v1.y);
                    h[3] = __floats2half2_rn(v1.z, v1.w);
                    *(uint4*)&C16[(size_t)row*N + col] = *(uint4*)h;
                } else {
                    *(float4*)&C[(size_t)row*N + col]     = v0;
                    *(float4*)&C[(size_t)row*N + col + 4] = v1;
                }
            }
            __syncwarp();
        }
    }
}

// ---------------- weight transpose+convert: out16[n*K+k] = in[k*N+n] ---------
__global__ void transpose_h(const float* __restrict__ in, __half* __restrict__ out,
                            int K, int N)
{
    __shared__ float t[32][33];
    int z = blockIdx.z;
    in  += (size_t)z * K * N;
    out += (size_t)z * K * N;
    int n0 = blockIdx.x * 32, k0 = blockIdx.y * 32;
    #pragma unroll
    for (int i = 0; i < 4; i++)
        t[threadIdx.y + i*8][threadIdx.x] =
            in[(size_t)(k0 + threadIdx.y + i*8) * N + n0 + threadIdx.x];
    __syncthreads();
    #pragma unroll
    for (int i = 0; i < 4; i++)
        out[(size_t)(n0 + threadIdx.y + i*8) * K + k0 + threadIdx.x] =
            __float2half(t[threadIdx.x][threadIdx.y + i*8]);
}

// interleave-transpose: out rows 2j = Wz[:,j], 2j+1 = Wh[:,j]  (per layer z)
__global__ void transpose_zh(const float* __restrict__ Wz,
                             const float* __restrict__ Wh,
                             __half* __restrict__ out)   // [L][1024][512]
{
    __shared__ float tz[32][33];
    __shared__ float th[32][33];
    int z = blockIdx.z;
    const float* wz = Wz + (size_t)z * DDIM * DDIM;
    const float* wh = Wh + (size_t)z * DDIM * DDIM;
    __half* o = out + (size_t)z * 2 * DDIM * DDIM;
    int j0 = blockIdx.x * 32, k0 = blockIdx.y * 32;
    #pragma unroll
    for (int i = 0; i < 4; i++) {
        int kk = threadIdx.y + i*8;
        tz[kk][threadIdx.x] = wz[(size_t)(k0 + kk) * DDIM + j0 + threadIdx.x];
        th[kk][threadIdx.x] = wh[(size_t)(k0 + kk) * DDIM + j0 + threadIdx.x];
    }
    __syncthreads();
    #pragma unroll
    for (int i = 0; i < 8; i++) {
        int nl = threadIdx.y + i*8;          // 0..63 local interleaved row
        int jl = nl >> 1;
        float val = (nl & 1) ? th[threadIdx.x][jl] : tz[threadIdx.x][jl];
        o[(size_t)(2*j0 + nl) * DDIM + k0 + threadIdx.x] = __float2half(val);
    }
}

// elementwise fp32 -> fp16 (pw_w is already [N][K])
__global__ void convert_h(const float* __restrict__ in, __half* __restrict__ out, int n)
{
    int i = blockIdx.x * blockDim.x + threadIdx.x;
    if (i < n) out[i] = __float2half(in[i]);
}

// ---------------- depthwise causal conv (K=4), fp16 out ----------------------
__global__ void dwconv_kernel(const float* __restrict__ x,
                              const float* __restrict__ w,
                              const float* __restrict__ wb,
                              __half* __restrict__ out)
{
    int idx = blockIdx.x * blockDim.x + threadIdx.x;
    if (idx >= MMR*DDIM) return;
    int c = idx % DDIM;
    int bs = idx / DDIM;
    int s = bs % SS;
    float acc = wb[c];
    #pragma unroll
    for (int k = 0; k < 4; k++) {
        int sp = s + k - 3;
        if (sp >= 0) acc += w[c*4 + k] * x[idx + (k-3)*DDIM];
    }
    out[idx] = __float2half(acc);
}

// ---------------- LayerNorm (512), warp-per-row; fp32 in -> fp16 out ---------
__global__ void ln_f2h(const float* __restrict__ in, __half* __restrict__ out,
                       const float* __restrict__ g, const float* __restrict__ b)
{
    int warp = threadIdx.x >> 5, lane = threadIdx.x & 31;
    int row = blockIdx.x * 8 + warp;
    const float* p = in + (size_t)row * DDIM;
    float vals[16];
    float s = 0.f;
    #pragma unroll
    for (int i = 0; i < 16; i++) { vals[i] = p[lane + i*32]; s += vals[i]; }
    #pragma unroll
    for (int o = 16; o > 0; o >>= 1) s += __shfl_xor_sync(0xffffffff, s, o);
    float mean = s * (1.f/DDIM);
    float vs = 0.f;
    #pragma unroll
    for (int i = 0; i < 16; i++) { float d = vals[i]-mean; vs += d*d; }
    #pragma unroll
    for (int o = 16; o > 0; o >>= 1) vs += __shfl_xor_sync(0xffffffff, vs, o);
    float inv = rsqrtf(vs * (1.f/DDIM) + 1e-5f);
    __half* q = out + (size_t)row * DDIM;
    #pragma unroll
    for (int i = 0; i < 16; i++) {
        int c = lane + i*32;
        q[c] = __float2half((vals[i]-mean) * inv * g[c] + b[c]);
    }
}

// LayerNorm fp16 in -> fp16 out (for mlp_in = LN(gru_in))
__global__ void ln_h2h(const __half* __restrict__ in, __half* __restrict__ out,
                       const float* __restrict__ g, const float* __restrict__ b)
{
    int warp = threadIdx.x >> 5, lane = threadIdx.x & 31;
    int row = blockIdx.x * 8 + warp;
    const __half* p = in + (size_t)row * DDIM;
    float vals[16];
    float s = 0.f;
    #pragma unroll
    for (int i = 0; i < 16; i++) { vals[i] = __half2float(p[lane + i*32]); s += vals[i]; }
    #pragma unroll
    for (int o = 16; o > 0; o >>= 1) s += __shfl_xor_sync(0xffffffff, s, o);
    float mean = s * (1.f/DDIM);
    float vs = 0.f;
    #pragma unroll
    for (int i = 0; i < 16; i++) { float d = vals[i]-mean; vs += d*d; }
    #pragma unroll
    for (int o = 16; o > 0; o >>= 1) vs += __shfl_xor_sync(0xffffffff, vs, o);
    float inv = rsqrtf(vs * (1.f/DDIM) + 1e-5f);
    __half* q = out + (size_t)row * DDIM;
    #pragma unroll
    for (int i = 0; i < 16; i++) {
        int c = lane + i*32;
        q[c] = __float2half((vals[i]-mean) * inv * g[c] + b[c]);
    }
}

// ---------------- scan pass1: read c,v (fp16) -> chunk carries P,V ----------
__global__ void scan_pass1(const __half* __restrict__ cb, const __half* __restrict__ vb,
                           float* __restrict__ Pb, float* __restrict__ Vb)
{
    int gid = blockIdx.x * blockDim.x + threadIdx.x;
    int b = gid / (DDIM*NCH);
    int r = gid - b*(DDIM*NCH);
    int chunk = r / DDIM;
    int d = r - chunk*DDIM;
    size_t base = ((size_t)b*SS + (size_t)chunk*CHK)*DDIM + d;
    float p = 1.f, v = 0.f;
    for (int i = 0; i < CHK; i++) {
        size_t o = base + (size_t)i*DDIM;
        float ci = __half2float(cb[o]);
        float vi = __half2float(vb[o]);
        v = fmaf(ci, v, vi);
        p *= ci;
    }
    int ch = (b*DDIM + d)*NCH + chunk;
    Pb[ch] = p; Vb[ch] = v;
}

__global__ void scan_pass2(const float* __restrict__ Pb, const float* __restrict__ Vb,
                           float* __restrict__ Hib)
{
    int ch = blockIdx.x * blockDim.x + threadIdx.x;
    if (ch >= BB*DDIM) return;
    float h = 0.5f;
    #pragma unroll
    for (int c = 0; c < NCH; c++) {
        Hib[ch*NCH + c] = h;
        h = fmaf(Pb[ch*NCH + c], h, Vb[ch*NCH + c]);
    }
}

__global__ void scan_pass3(const __half* __restrict__ cb, const __half* __restrict__ vb,
                           const float* __restrict__ Hib, float* __restrict__ xb)
{
    int gid = blockIdx.x * blockDim.x + threadIdx.x;
    int b = gid / (DDIM*NCH);
    int r = gid - b*(DDIM*NCH);
    int chunk = r / DDIM;
    int d = r - chunk*DDIM;
    size_t base = ((size_t)b*SS + (size_t)chunk*CHK)*DDIM + d;
    float h = Hib[(b*DDIM + d)*NCH + chunk];
    for (int i = 0; i < CHK; i++) {
        size_t o = base + (size_t)i*DDIM;
        h = fmaf(__half2float(cb[o]), h, __half2float(vb[o]));
        xb[o] += h;
    }
}

// -------------------------------- launch ------------------------------------
extern "C" void kernel_launch(void* const* d_in, const int* in_sizes, int n_in,
                              void* d_out, int out_size)
{
    const float* x     = (const float*)d_in[0];
    const float* dw_w  = (const float*)d_in[1];
    const float* dw_b  = (const float*)d_in[2];
    const float* pw_w  = (const float*)d_in[3];
    const float* pw_b  = (const float*)d_in[4];
    const float* ln1_g = (const float*)d_in[5];
    const float* ln1_b = (const float*)d_in[6];
    const float* Wz    = (const float*)d_in[7];
    const float* Wh    = (const float*)d_in[8];
    const float* lng   = (const float*)d_in[9];
    const float* lnb   = (const float*)d_in[10];
    const float* ln2_g = (const float*)d_in[11];
    const float* ln2_b = (const float*)d_in[12];
    const float* W1    = (const float*)d_in[13];
    const float* b1    = (const float*)d_in[14];
    const float* W2    = (const float*)d_in[15];
    const float* b2    = (const float*)d_in[16];
    float* out = (float*)d_out;

    float *xbuf, *Pb, *Vb, *Hib;
    __half *c16, *v16, *gin16, *cin16, *h16, *Wzh16, *W1T16, *W2T16, *pw16;
    cudaGetSymbolAddress((void**)&xbuf, g_xbuf);
    cudaGetSymbolAddress((void**)&Pb,   g_P);
    cudaGetSymbolAddress((void**)&Vb,   g_V);
    cudaGetSymbolAddress((void**)&Hib,  g_Hi);
    cudaGetSymbolAddress((void**)&c16,  g_c16);
    cudaGetSymbolAddress((void**)&v16,  g_v16);
    cudaGetSymbolAddress((void**)&gin16, g_gin16);
    cudaGetSymbolAddress((void**)&cin16, g_cin16);
    cudaGetSymbolAddress((void**)&h16,   g_h16);
    cudaGetSymbolAddress((void**)&Wzh16, g_Wzh16);
    cudaGetSymbolAddress((void**)&W1T16, g_W1T16);
    cudaGetSymbolAddress((void**)&W2T16, g_W2T16);
    cudaGetSymbolAddress((void**)&pw16,  g_pw16);

    cudaFuncSetAttribute(hgemm_kernel,
        cudaFuncAttributeMaxDynamicSharedMemorySize, SMEMSZ);

    const int NELT = MMR*DDIM;
    dim3 eltGrid((NELT + 255)/256);
    dim3 tb(32, 8);

    // 0) weight convert/transpose to fp16
    transpose_zh<<<dim3(DDIM/32, DDIM/32, LL), tb>>>(Wz, Wh, Wzh16);
    transpose_h<<<dim3(HH/32, DDIM/32, 1),   tb>>>(W1, W1T16, DDIM, HH);
    transpose_h<<<dim3(DDIM/32, HH/32, 1),   tb>>>(W2, W2T16, HH, DDIM);
    convert_h<<<(DDIM*DDIM + 255)/256, 256>>>(pw_w, pw16, DDIM*DDIM);

    // 1) depthwise conv -> cin16 (fp16)
    dwconv_kernel<<<eltGrid, 256>>>(x, dw_w, dw_b, cin16);

    // 2) pointwise conv + pw_b + residual x -> xbuf (fp32)
    hgemm_kernel<<<dim3(DDIM/128, MMR/128), NTHR, SMEMSZ>>>(
        cin16, pw16, xbuf, nullptr, nullptr, nullptr,
        MMR, DDIM, DDIM, pw_b, x, 0);

    // 3) gru_in = LN(xbuf, ln1) -> gin16
    ln_f2h<<<MMR/8, 256>>>(xbuf, gin16, ln1_g, ln1_b);

    // 4) GRU layers: ONE combined GEMM (N=1024, interleaved) w/ fused gating
    for (int l = 0; l < LL; l++) {
        hgemm_kernel<<<dim3(2*DDIM/128, MMR/128), NTHR, SMEMSZ>>>(
            gin16, Wzh16 + (size_t)l*2*DDIM*DDIM, nullptr, nullptr, c16, v16,
            MMR, 2*DDIM, DDIM, nullptr, nullptr, 0);
        scan_pass1<<<(BB*DDIM*NCH)/256, 256>>>(c16, v16, Pb, Vb);
        scan_pass2<<<(BB*DDIM + 255)/256, 256>>>(Pb, Vb, Hib);
        scan_pass3<<<(BB*DDIM*NCH)/256, 256>>>(c16, v16, Hib, xbuf);
        ln_f2h<<<MMR/8, 256>>>(xbuf, gin16, lng + l*DDIM, lnb + l*DDIM);
    }

    // 5) mlp_in = LN(gin16, ln2) -> cin16 (fp16)
    ln_h2h<<<MMR/8, 256>>>(gin16, cin16, ln2_g, ln2_b);

    // 6) hidden = relu(mlp_in @ W1 + b1) -> h16 (fp16)
    hgemm_kernel<<<dim3(HH/128, MMR/128), NTHR, SMEMSZ>>>(
        cin16, W1T16, nullptr, h16, nullptr, nullptr,
        MMR, HH, DDIM, b1, nullptr, 1);

    // 7) out = hidden @ W2 + b2 + xbuf
    hgemm_kernel<<<dim3(DDIM/128, MMR/128), NTHR, SMEMSZ>>>(
        h16, W2T16, out, nullptr, nullptr, nullptr,
        MMR, DDIM, HH, b2, xbuf, 0);
}

// round 14
// speedup vs baseline: 1.1701x; 1.1701x over previous
#include <cuda_runtime.h>
#include <cstdint>
#include <math.h>
#include <cuda_fp16.h>
#include <mma.h>
using namespace nvcuda;

// Fixed problem shapes
#define BB   4
#define SS   4096
#define DDIM 512
#define HH   2048
#define LL   3
#define MMR  (BB*SS)      // 16384 rows
#define CHK  128          // scan chunk length (per-thread serial)
#define NCH  (SS/CHK)     // 32 chunks per sequence

// GEMM tiling: 128x128 CTA tile, 8 warps (64x32), KTILE=64, 3-stage pipeline
#define KTILE 64
#define LDSA  72               // smem stride in halfs (64 + 8 pad)
#define ATILE (128*LDSA)       // 9216 halfs = 18432 B
#define STAGE (2*ATILE)        // A+B per stage (halfs)
#define NSTG  3
#define SMEMSZ (NSTG*STAGE*2)  // 110592 bytes  (epilogue aliases stage 0)
#define NTHR  256

// ---------------- scratch (static device arrays; no allocation) --------------
__device__ float  g_xbuf[MMR*DDIM];   // residual stream (fp32)
__device__ float  g_P [BB*DDIM*NCH];
__device__ float  g_V [BB*DDIM*NCH];
__device__ float  g_Hi[BB*DDIM*NCH];
__device__ __half g_c16 [MMR*DDIM];   // gate c (fp16)
__device__ __half g_v16 [MMR*DDIM];   // gate v (fp16)
__device__ __half g_gin16[MMR*DDIM];  // LN outputs (GEMM A operand)
__device__ __half g_cin16[MMR*DDIM];  // dwconv out / mlp_in (GEMM A operand)
__device__ __half g_h16 [MMR*HH];     // MLP hidden (fp16)
// fp16 transposed weights [N][K]
__device__ __half g_Wzh16[LL*2*DDIM*DDIM];  // interleaved [1024][512] per layer
__device__ __half g_W1T16[HH*DDIM];
__device__ __half g_W2T16[DDIM*HH];
__device__ __half g_pw16 [DDIM*DDIM];

// ---------------- fp16 tensor-core GEMM, 128x128x64, 8 warps, 3-stage --------
// C[m,n] = sum_k A[m,k] * Bt[n,k]   (A fp16 [M,K], Bt fp16 [N,K], fp32 accum)
__device__ __forceinline__ void cpasync16(void* dst, const void* src)
{
    unsigned int d = (unsigned int)__cvta_generic_to_shared(dst);
    asm volatile("cp.async.cg.shared.global [%0], [%1], 16;\n" :: "r"(d), "l"(src));
}

__global__ void __launch_bounds__(NTHR, 2)
hgemm_kernel(const __half* __restrict__ A, const __half* __restrict__ Bt,
             float* __restrict__ C, __half* __restrict__ C16,
             __half* __restrict__ gateC, __half* __restrict__ gateV,
             int M, int N, int K,
             const float* __restrict__ bias, const float* __restrict__ resid,
             int dorelu)
{
    extern __shared__ __half smh[];
    float* epist = (float*)smh;       // aliases stage 0 (used post-mainloop)

    const int tid = threadIdx.x;
    const int wid = tid >> 5;
    const int lane = tid & 31;
    const int bm = blockIdx.y * 128;
    const int bn = blockIdx.x * 128;
    const int wm = (wid >> 2) * 64;   // warp grid 2(m) x 4(n)
    const int wn = (wid & 3) * 32;
    float* wbuf = epist + wid*256;    // per-warp 16x16 staging

    wmma::fragment<wmma::accumulator, 16, 16, 16, float> acc[4][2];
    #pragma unroll
    for (int i = 0; i < 4; i++)
        #pragma unroll
        for (int j = 0; j < 2; j++) wmma::fill_fragment(acc[i][j], 0.f);

    // ---- stage loaders: 128 rows x 64 halfs = 1024 16B-chunks -> 4/thread ---
    auto loadStage = [&](int stg, int k0) {
        __half* As = smh + stg*STAGE;
        __half* Bs = As + ATILE;
        #pragma unroll
        for (int i = 0; i < 4; i++) {
            int idx = tid + i*NTHR;
            int r = idx >> 3, c8 = (idx & 7) * 8;
            cpasync16(As + r*LDSA + c8, A + (size_t)(bm + r)*K + k0 + c8);
        }
        #pragma unroll
        for (int i = 0; i < 4; i++) {
            int idx = tid + i*NTHR;
            int r = idx >> 3, c8 = (idx & 7) * 8;
            cpasync16(Bs + r*LDSA + c8, Bt + (size_t)(bn + r)*K + k0 + c8);
        }
        asm volatile("cp.async.commit_group;\n");
    };

    const int nk = K / KTILE;
    loadStage(0, 0);
    if (nk > 1) loadStage(1, KTILE);

    for (int kt = 0; kt < nk; kt++) {
        if (kt + 1 < nk) {
            asm volatile("cp.async.wait_group 1;\n");   // stage kt ready
        } else {
            asm volatile("cp.async.wait_group 0;\n");
        }
        __syncthreads();
        if (kt + 2 < nk) loadStage((kt+2) % NSTG, (kt+2)*KTILE);

        const __half* a = smh + (kt % NSTG)*STAGE;
        const __half* b = a + ATILE;
        #pragma unroll
        for (int ks = 0; ks < 4; ks++) {
            const int kk = ks * 16;
            wmma::fragment<wmma::matrix_a, 16, 16, 16, half, wmma::row_major> af[4];
            #pragma unroll
            for (int i = 0; i < 4; i++)
                wmma::load_matrix_sync(af[i], a + (wm + i*16)*LDSA + kk, LDSA);
            wmma::fragment<wmma::matrix_b, 16, 16, 16, half, wmma::col_major> bf[2];
            #pragma unroll
            for (int j = 0; j < 2; j++)
                wmma::load_matrix_sync(bf[j], b + (wn + j*16)*LDSA + kk, LDSA);
            #pragma unroll
            for (int i = 0; i < 4; i++)
                #pragma unroll
                for (int j = 0; j < 2; j++)
                    wmma::mma_sync(acc[i][j], af[i], bf[j], acc[i][j]);
        }
    }
    __syncthreads();   // protect epilogue staging (aliases stage 0)

    // ---- epilogue: per-warp 16x16 staging ----
    #pragma unroll
    for (int i = 0; i < 4; i++) {
        #pragma unroll
        for (int j = 0; j < 2; j++) {
            wmma::store_matrix_sync(wbuf, acc[i][j], 16, wmma::mem_row_major);
            __syncwarp();
            int r = lane >> 1, c = (lane & 1) * 8;
            int row = bm + wm + i*16 + r;
            int col = bn + wn + j*16 + c;
            float4 v0 = *(float4*)&wbuf[r*16 + c];
            float4 v1 = *(float4*)&wbuf[r*16 + c + 4];
            if (gateC) {
                // interleaved cols: (k0,a0,k1,a1,...) -> 4 (k,a) pairs
                float kk_[4] = { v0.x, v0.z, v1.x, v1.z };
                float aa_[4] = { v0.y, v0.w, v1.y, v1.w };
                __half cw[4], vw[4];
                #pragma unroll
                for (int t = 0; t < 4; t++) {
                    float e  = __expf(kk_[t]);
                    float ci = 1.f / (1.f + e);      // sigmoid(-k)
                    float zi = e * ci;               // sigmoid(k)
                    float a  = aa_[t];
                    float gg = (a >= 0.f) ? (a + 0.5f)
                                          : (1.f / (1.f + __expf(-a)));
                    cw[t] = __float2half(ci);
                    vw[t] = __float2half(zi * gg);
                }
                int p = col >> 1;    // pair index 0..511
                *(uint2*)&gateC[(size_t)row*DDIM + p] = *(uint2*)cw;
                *(uint2*)&gateV[(size_t)row*DDIM + p] = *(uint2*)vw;
            } else {
                if (bias) {
                    float4 b0 = *(const float4*)&bias[col];
                    float4 b1 = *(const float4*)&bias[col+4];
                    v0.x += b0.x; v0.y += b0.y; v0.z += b0.z; v0.w += b0.w;
                    v1.x += b1.x; v1.y += b1.y; v1.z += b1.z; v1.w += b1.w;
                }
                if (dorelu) {
                    v0.x = fmaxf(v0.x, 0.f); v0.y = fmaxf(v0.y, 0.f);
                    v0.z = fmaxf(v0.z, 0.f); v0.w = fmaxf(v0.w, 0.f);
                    v1.x = fmaxf(v1.x, 0.f); v1.y = fmaxf(v1.y, 0.f);
                    v1.z = fmaxf(v1.z, 0.f); v1.w = fmaxf(v1.w, 0.f);
                }
                if (resid) {
                    float4 r0 = *(const float4*)&resid[(size_t)row*N + col];
                    float4 r1 = *(const float4*)&resid[(size_t)row*N + col + 4];
                    v0.x += r0.x; v0.y += r0.y; v0.z += r0.z; v0.w += r0.w;
                    v1.x += r1.x; v1.y += r1.y; v1.z += r1.z; v1.w += r1.w;
                }
                if (C16) {
                    __half2 h[4];
                    h[0] = __floats2half2_rn(v0.x, v0.y);
                    h[1] = __floats2half2_rn(v0.z, v0.w);
                    h[2] = __floats2half2_rn(v1.x, v1.y);
                    h[3] = __floats2half2_rn(v1.z, v1.w);
                    *(uint4*)&C16[(size_t)row*N + col] = *(uint4*)h;
                } else {
                    *(float4*)&C[(size_t)row*N + col]     = v0;
                    *(float4*)&C[(size_t)row*N + col + 4] = v1;
                }
            }
            __syncwarp();
        }
    }
}

// ---------------- weight transpose+convert: out16[n*K+k] = in[k*N+n] ---------
__global__ void transpose_h(const float* __restrict__ in, __half* __restrict__ out,
                            int K, int N)
{
    __shared__ float t[32][33];
    int z = blockIdx.z;
    in  += (size_t)z * K * N;
    out += (size_t)z * K * N;
    int n0 = blockIdx.x * 32, k0 = blockIdx.y * 32;
    #pragma unroll
    for (int i = 0; i < 4; i++)
        t[threadIdx.y + i*8][threadIdx.x] =
            in[(size_t)(k0 + threadIdx.y + i*8) * N + n0 + threadIdx.x];
    __syncthreads();
    #pragma unroll
    for (int i = 0; i < 4; i++)
        out[(size_t)(n0 + threadIdx.y + i*8) * K + k0 + threadIdx.x] =
            __float2half(t[threadIdx.x][threadIdx.y + i*8]);
}

// interleave-transpose: out rows 2j = Wz[:,j], 2j+1 = Wh[:,j]  (per layer z)
__global__ void transpose_zh(const float* __restrict__ Wz,
                             const float* __restrict__ Wh,
                             __half* __restrict__ out)   // [L][1024][512]
{
    __shared__ float tz[32][33];
    __shared__ float th[32][33];
    int z = blockIdx.z;
    const float* wz = Wz + (size_t)z * DDIM * DDIM;
    const float* wh = Wh + (size_t)z * DDIM * DDIM;
    __half* o = out + (size_t)z * 2 * DDIM * DDIM;
    int j0 = blockIdx.x * 32, k0 = blockIdx.y * 32;
    #pragma unroll
    for (int i = 0; i < 4; i++) {
        int kk = threadIdx.y + i*8;
        tz[kk][threadIdx.x] = wz[(size_t)(k0 + kk) * DDIM + j0 + threadIdx.x];
        th[kk][threadIdx.x] = wh[(size_t)(k0 + kk) * DDIM + j0 + threadIdx.x];
    }
    __syncthreads();
    #pragma unroll
    for (int i = 0; i < 8; i++) {
        int nl = threadIdx.y + i*8;          // 0..63 local interleaved row
        int jl = nl >> 1;
        float val = (nl & 1) ? th[threadIdx.x][jl] : tz[threadIdx.x][jl];
        o[(size_t)(2*j0 + nl) * DDIM + k0 + threadIdx.x] = __float2half(val);
    }
}

// elementwise fp32 -> fp16 (pw_w is already [N][K])
__global__ void convert_h(const float* __restrict__ in, __half* __restrict__ out, int n)
{
    int i = blockIdx.x * blockDim.x + threadIdx.x;
    if (i < n) out[i] = __float2half(in[i]);
}

// ---------------- depthwise causal conv (K=4), fp16 out ----------------------
__global__ void dwconv_kernel(const float* __restrict__ x,
                              const float* __restrict__ w,
                              const float* __restrict__ wb,
                              __half* __restrict__ out)
{
    int idx = blockIdx.x * blockDim.x + threadIdx.x;
    if (idx >= MMR*DDIM) return;
    int c = idx % DDIM;
    int bs = idx / DDIM;
    int s = bs % SS;
    float acc = wb[c];
    #pragma unroll
    for (int k = 0; k < 4; k++) {
        int sp = s + k - 3;
        if (sp >= 0) acc += w[c*4 + k] * x[idx + (k-3)*DDIM];
    }
    out[idx] = __float2half(acc);
}

// ---------------- LayerNorm (512), warp-per-row; fp32 in -> fp16 out ---------
__global__ void ln_f2h(const float* __restrict__ in, __half* __restrict__ out,
                       const float* __restrict__ g, const float* __restrict__ b)
{
    int warp = threadIdx.x >> 5, lane = threadIdx.x & 31;
    int row = blockIdx.x * 8 + warp;
    const float* p = in + (size_t)row * DDIM;
    float vals[16];
    float s = 0.f;
    #pragma unroll
    for (int i = 0; i < 16; i++) { vals[i] = p[lane + i*32]; s += vals[i]; }
    #pragma unroll
    for (int o = 16; o > 0; o >>= 1) s += __shfl_xor_sync(0xffffffff, s, o);
    float mean = s * (1.f/DDIM);
    float vs = 0.f;
    #pragma unroll
    for (int i = 0; i < 16; i++) { float d = vals[i]-mean; vs += d*d; }
    #pragma unroll
    for (int o = 16; o > 0; o >>= 1) vs += __shfl_xor_sync(0xffffffff, vs, o);
    float inv = rsqrtf(vs * (1.f/DDIM) + 1e-5f);
    __half* q = out + (size_t)row * DDIM;
    #pragma unroll
    for (int i = 0; i < 16; i++) {
        int c = lane + i*32;
        q[c] = __float2half((vals[i]-mean) * inv * g[c] + b[c]);
    }
}

// LayerNorm fp16 in -> fp16 out (for mlp_in = LN(gru_in))
__global__ void ln_h2h(const __half* __restrict__ in, __half* __restrict__ out,
                       const float* __restrict__ g, const float* __restrict__ b)
{
    int warp = threadIdx.x >> 5, lane = threadIdx.x & 31;
    int row = blockIdx.x * 8 + warp;
    const __half* p = in + (size_t)row * DDIM;
    float vals[16];
    float s = 0.f;
    #pragma unroll
    for (int i = 0; i < 16; i++) { vals[i] = __half2float(p[lane + i*32]); s += vals[i]; }
    #pragma unroll
    for (int o = 16; o > 0; o >>= 1) s += __shfl_xor_sync(0xffffffff, s, o);
    float mean = s * (1.f/DDIM);
    float vs = 0.f;
    #pragma unroll
    for (int i = 0; i < 16; i++) { float d = vals[i]-mean; vs += d*d; }
    #pragma unroll
    for (int o = 16; o > 0; o >>= 1) vs += __shfl_xor_sync(0xffffffff, vs, o);
    float inv = rsqrtf(vs * (1.f/DDIM) + 1e-5f);
    __half* q = out + (size_t)row * DDIM;
    #pragma unroll
    for (int i = 0; i < 16; i++) {
        int c = lane + i*32;
        q[c] = __float2half((vals[i]-mean) * inv * g[c] + b[c]);
    }
}

// ---------------- scan pass1: read c,v (fp16) -> chunk carries P,V ----------
__global__ void scan_pass1(const __half* __restrict__ cb, const __half* __restrict__ vb,
                           float* __restrict__ Pb, float* __restrict__ Vb)
{
    int gid = blockIdx.x * blockDim.x + threadIdx.x;
    int b = gid / (DDIM*NCH);
    int r = gid - b*(DDIM*NCH);
    int chunk = r / DDIM;
    int d = r - chunk*DDIM;
    size_t base = ((size_t)b*SS + (size_t)chunk*CHK)*DDIM + d;
    float p = 1.f, v = 0.f;
    for (int i = 0; i < CHK; i++) {
        size_t o = base + (size_t)i*DDIM;
        float ci = __half2float(cb[o]);
        float vi = __half2float(vb[o]);
        v = fmaf(ci, v, vi);
        p *= ci;
    }
    int ch = (b*DDIM + d)*NCH + chunk;
    Pb[ch] = p; Vb[ch] = v;
}

__global__ void scan_pass2(const float* __restrict__ Pb, const float* __restrict__ Vb,
                           float* __restrict__ Hib)
{
    int ch = blockIdx.x * blockDim.x + threadIdx.x;
    if (ch >= BB*DDIM) return;
    float h = 0.5f;
    #pragma unroll
    for (int c = 0; c < NCH; c++) {
        Hib[ch*NCH + c] = h;
        h = fmaf(Pb[ch*NCH + c], h, Vb[ch*NCH + c]);
    }
}

__global__ void scan_pass3(const __half* __restrict__ cb, const __half* __restrict__ vb,
                           const float* __restrict__ Hib, float* __restrict__ xb)
{
    int gid = blockIdx.x * blockDim.x + threadIdx.x;
    int b = gid / (DDIM*NCH);
    int r = gid - b*(DDIM*NCH);
    int chunk = r / DDIM;
    int d = r - chunk*DDIM;
    size_t base = ((size_t)b*SS + (size_t)chunk*CHK)*DDIM + d;
    float h = Hib[(b*DDIM + d)*NCH + chunk];
    for (int i = 0; i < CHK; i++) {
        size_t o = base + (size_t)i*DDIM;
        h = fmaf(__half2float(cb[o]), h, __half2float(vb[o]));
        xb[o] += h;
    }
}

// -------------------------------- launch ------------------------------------
extern "C" void kernel_launch(void* const* d_in, const int* in_sizes, int n_in,
                              void* d_out, int out_size)
{
    const float* x     = (const float*)d_in[0];
    const float* dw_w  = (const float*)d_in[1];
    const float* dw_b  = (const float*)d_in[2];
    const float* pw_w  = (const float*)d_in[3];
    const float* pw_b  = (const float*)d_in[4];
    const float* ln1_g = (const float*)d_in[5];
    const float* ln1_b = (const float*)d_in[6];
    const float* Wz    = (const float*)d_in[7];
    const float* Wh    = (const float*)d_in[8];
    const float* lng   = (const float*)d_in[9];
    const float* lnb   = (const float*)d_in[10];
    const float* ln2_g = (const float*)d_in[11];
    const float* ln2_b = (const float*)d_in[12];
    const float* W1    = (const float*)d_in[13];
    const float* b1    = (const float*)d_in[14];
    const float* W2    = (const float*)d_in[15];
    const float* b2    = (const float*)d_in[16];
    float* out = (float*)d_out;

    float *xbuf, *Pb, *Vb, *Hib;
    __half *c16, *v16, *gin16, *cin16, *h16, *Wzh16, *W1T16, *W2T16, *pw16;
    cudaGetSymbolAddress((void**)&xbuf, g_xbuf);
    cudaGetSymbolAddress((void**)&Pb,   g_P);
    cudaGetSymbolAddress((void**)&Vb,   g_V);
    cudaGetSymbolAddress((void**)&Hib,  g_Hi);
    cudaGetSymbolAddress((void**)&c16,  g_c16);
    cudaGetSymbolAddress((void**)&v16,  g_v16);
    cudaGetSymbolAddress((void**)&gin16, g_gin16);
    cudaGetSymbolAddress((void**)&cin16, g_cin16);
    cudaGetSymbolAddress((void**)&h16,   g_h16);
    cudaGetSymbolAddress((void**)&Wzh16, g_Wzh16);
    cudaGetSymbolAddress((void**)&W1T16, g_W1T16);
    cudaGetSymbolAddress((void**)&W2T16, g_W2T16);
    cudaGetSymbolAddress((void**)&pw16,  g_pw16);

    cudaFuncSetAttribute(hgemm_kernel,
        cudaFuncAttributeMaxDynamicSharedMemorySize, SMEMSZ);

    const int NELT = MMR*DDIM;
    dim3 eltGrid((NELT + 255)/256);
    dim3 tb(32, 8);

    // 0) weight convert/transpose to fp16
    transpose_zh<<<dim3(DDIM/32, DDIM/32, LL), tb>>>(Wz, Wh, Wzh16);
    transpose_h<<<dim3(HH/32, DDIM/32, 1),   tb>>>(W1, W1T16, DDIM, HH);
    transpose_h<<<dim3(DDIM/32, HH/32, 1),   tb>>>(W2, W2T16, HH, DDIM);
    convert_h<<<(DDIM*DDIM + 255)/256, 256>>>(pw_w, pw16, DDIM*DDIM);

    // 1) depthwise conv -> cin16 (fp16)
    dwconv_kernel<<<eltGrid, 256>>>(x, dw_w, dw_b, cin16);

    // 2) pointwise conv + pw_b + residual x -> xbuf (fp32)
    hgemm_kernel<<<dim3(DDIM/128, MMR/128), NTHR, SMEMSZ>>>(
        cin16, pw16, xbuf, nullptr, nullptr, nullptr,
        MMR, DDIM, DDIM, pw_b, x, 0);

    // 3) gru_in = LN(xbuf, ln1) -> gin16
    ln_f2h<<<MMR/8, 256>>>(xbuf, gin16, ln1_g, ln1_b);

    // 4) GRU layers: ONE combined GEMM (N=1024, interleaved) w/ fused gating
    for (int l = 0; l < LL; l++) {
        hgemm_kernel<<<dim3(2*DDIM/128, MMR/128), NTHR, SMEMSZ>>>(
            gin16, Wzh16 + (size_t)l*2*DDIM*DDIM, nullptr, nullptr, c16, v16,
            MMR, 2*DDIM, DDIM, nullptr, nullptr, 0);
        scan_pass1<<<(BB*DDIM*NCH)/256, 256>>>(c16, v16, Pb, Vb);
        scan_pass2<<<(BB*DDIM + 255)/256, 256>>>(Pb, Vb, Hib);
        scan_pass3<<<(BB*DDIM*NCH)/256, 256>>>(c16, v16, Hib, xbuf);
        ln_f2h<<<MMR/8, 256>>>(xbuf, gin16, lng + l*DDIM, lnb + l*DDIM);
    }

    // 5) mlp_in = LN(gin16, ln2) -> cin16 (fp16)
    ln_h2h<<<MMR/8, 256>>>(gin16, cin16, ln2_g, ln2_b);

    // 6) hidden = relu(mlp_in @ W1 + b1) -> h16 (fp16)
    hgemm_kernel<<<dim3(HH/128, MMR/128), NTHR, SMEMSZ>>>(
        cin16, W1T16, nullptr, h16, nullptr, nullptr,
        MMR, HH, DDIM, b1, nullptr, 1);

    // 7) out = hidden @ W2 + b2 + xbuf
    hgemm_kernel<<<dim3(DDIM/128, MMR/128), NTHR, SMEMSZ>>>(
        h16, W2T16, out, nullptr, nullptr, nullptr,
        MMR, DDIM, HH, b2, xbuf, 0);
}